// round 1
// baseline (speedup 1.0000x reference)
#include <cuda_runtime.h>
#include <cstdint>

// ---------------------------------------------------------------------------
// LoRA attention, fp32 baseline.
//   q/k/v = x @ (W + B·A)^T   (LoRA folded into weights)
//   flash attention, scale 1/8
//   out  = ctx @ (Wo + Bo·Ao)^T + bo
// ---------------------------------------------------------------------------

#define CD   1280
#define RD   4
#define BB   2
#define SS   2048
#define MM   (BB * SS)      // 4096
#define HH   20
#define DD   64
#define NQKV (3 * CD)       // 3840

// __device__ scratch (no allocs allowed in kernel_launch)
__device__ float g_Wqkv[NQKV * CD];   // folded [Wq;Wk;Wv], row-major [n][c]
__device__ float g_Wo[CD * CD];       // folded Wo
__device__ float g_qkv[MM * NQKV];    // [m][3C]  (q | k | v)
__device__ float g_ctx[MM * CD];      // attention output

// ---------------------------------------------------------------------------
// Fold LoRA into weights: W_eff[n][c] = W[n][c] + sum_r B[n][r]*A[r][c]
// ---------------------------------------------------------------------------
__global__ void fold_qkv_kernel(const float* __restrict__ Wq, const float* __restrict__ Wk,
                                const float* __restrict__ Wv,
                                const float* __restrict__ Aq, const float* __restrict__ Bq,
                                const float* __restrict__ Ak, const float* __restrict__ Bk,
                                const float* __restrict__ Av, const float* __restrict__ Bv) {
    int idx = blockIdx.x * blockDim.x + threadIdx.x;
    if (idx >= NQKV * CD) return;
    int n = idx / CD;
    int c = idx - n * CD;
    const float *W, *A, *B;
    int j;
    if (n < CD)          { W = Wq; A = Aq; B = Bq; j = n; }
    else if (n < 2 * CD) { W = Wk; A = Ak; B = Bk; j = n - CD; }
    else                 { W = Wv; A = Av; B = Bv; j = n - 2 * CD; }
    float acc = W[j * CD + c];
#pragma unroll
    for (int r = 0; r < RD; r++)
        acc = fmaf(B[j * RD + r], A[r * CD + c], acc);
    g_Wqkv[idx] = acc;
}

__global__ void fold_o_kernel(const float* __restrict__ Wo,
                              const float* __restrict__ Ao, const float* __restrict__ Bo) {
    int idx = blockIdx.x * blockDim.x + threadIdx.x;
    if (idx >= CD * CD) return;
    int j = idx / CD;
    int c = idx - j * CD;
    float acc = Wo[idx];
#pragma unroll
    for (int r = 0; r < RD; r++)
        acc = fmaf(Bo[j * RD + r], Ao[r * CD + c], acc);
    g_Wo[idx] = acc;
}

// ---------------------------------------------------------------------------
// SGEMM: C[m][n] = sum_k A[m][k] * Bw[n][k]   (both K-contiguous, "NT")
// 128x128 tile, BK=8, 256 threads, 8x8 per thread (4+4 column split).
// ---------------------------------------------------------------------------
template <bool ADD_BIAS>
__global__ __launch_bounds__(256)
void sgemm_nt_kernel(const float* __restrict__ A, const float* __restrict__ Bw,
                     float* __restrict__ Cmat, int K, int N,
                     const float* __restrict__ bias) {
    __shared__ float As[8][128];
    __shared__ float Bs[8][128];

    const int tid = threadIdx.x;
    const int tx = tid & 15;        // 0..15
    const int ty = tid >> 4;        // 0..15
    const int blockRow = blockIdx.y * 128;
    const int blockCol = blockIdx.x * 128;

    const int lr = tid >> 1;        // 0..127 : row within tile for loads
    const int lk = (tid & 1) * 4;   // 0 or 4 : k offset

    const float* aPtr = A  + (size_t)(blockRow + lr) * K + lk;
    const float* bPtr = Bw + (size_t)(blockCol + lr) * K + lk;

    float4 aReg = *(const float4*)aPtr;
    float4 bReg = *(const float4*)bPtr;

    float acc[8][8];
#pragma unroll
    for (int i = 0; i < 8; i++)
#pragma unroll
        for (int j = 0; j < 8; j++) acc[i][j] = 0.f;

    const int nt = K / 8;
    for (int t = 0; t < nt; t++) {
        __syncthreads();
        As[lk + 0][lr] = aReg.x; As[lk + 1][lr] = aReg.y;
        As[lk + 2][lr] = aReg.z; As[lk + 3][lr] = aReg.w;
        Bs[lk + 0][lr] = bReg.x; Bs[lk + 1][lr] = bReg.y;
        Bs[lk + 2][lr] = bReg.z; Bs[lk + 3][lr] = bReg.w;
        __syncthreads();

        if (t + 1 < nt) {
            aReg = *(const float4*)(aPtr + (size_t)(t + 1) * 8);
            bReg = *(const float4*)(bPtr + (size_t)(t + 1) * 8);
        }

#pragma unroll
        for (int k = 0; k < 8; k++) {
            float4 a0 = *(const float4*)&As[k][ty * 8];
            float4 a1 = *(const float4*)&As[k][ty * 8 + 4];
            float4 b0 = *(const float4*)&Bs[k][tx * 4];
            float4 b1 = *(const float4*)&Bs[k][64 + tx * 4];
            float av[8] = {a0.x, a0.y, a0.z, a0.w, a1.x, a1.y, a1.z, a1.w};
            float bv[8] = {b0.x, b0.y, b0.z, b0.w, b1.x, b1.y, b1.z, b1.w};
#pragma unroll
            for (int i = 0; i < 8; i++)
#pragma unroll
                for (int j = 0; j < 8; j++)
                    acc[i][j] = fmaf(av[i], bv[j], acc[i][j]);
        }
    }

#pragma unroll
    for (int i = 0; i < 8; i++) {
        int row = blockRow + ty * 8 + i;
        int c0 = blockCol + tx * 4;
        int c1 = blockCol + 64 + tx * 4;
        float4 v0 = make_float4(acc[i][0], acc[i][1], acc[i][2], acc[i][3]);
        float4 v1 = make_float4(acc[i][4], acc[i][5], acc[i][6], acc[i][7]);
        if (ADD_BIAS) {
            v0.x += bias[c0 + 0]; v0.y += bias[c0 + 1];
            v0.z += bias[c0 + 2]; v0.w += bias[c0 + 3];
            v1.x += bias[c1 + 0]; v1.y += bias[c1 + 1];
            v1.z += bias[c1 + 2]; v1.w += bias[c1 + 3];
        }
        *(float4*)&Cmat[(size_t)row * N + c0] = v0;
        *(float4*)&Cmat[(size_t)row * N + c1] = v1;
    }
}

// ---------------------------------------------------------------------------
// Flash attention: one thread == one query row (softmax state thread-local).
// Block = 128 q-rows; K/V tiles of 32 rows in smem; scores chunked by 16.
// q is pre-scaled by 1/sqrt(64)=0.125.
// ---------------------------------------------------------------------------
__global__ __launch_bounds__(128)
void attn_kernel() {
    const int b  = blockIdx.z;
    const int h  = blockIdx.y;
    const int qt = blockIdx.x;
    const int tid = threadIdx.x;
    const int qrow = qt * 128 + tid;

    __shared__ float Ks[32][64];
    __shared__ float Vs[32][64];

    const float* qptr = g_qkv + (size_t)(b * SS + qrow) * NQKV + h * DD;
    float4 q[16];
#pragma unroll
    for (int i = 0; i < 16; i++) {
        float4 t = *(const float4*)(qptr + i * 4);
        t.x *= 0.125f; t.y *= 0.125f; t.z *= 0.125f; t.w *= 0.125f;
        q[i] = t;
    }

    float4 o[16];
#pragma unroll
    for (int i = 0; i < 16; i++) o[i] = make_float4(0.f, 0.f, 0.f, 0.f);
    float m = -1e30f;
    float l = 0.f;

    const float* kbase = g_qkv + (size_t)(b * SS) * NQKV + CD + h * DD;
    const float* vbase = kbase + CD;

    const int lj = tid >> 2;        // 0..31 tile row
    const int lc = (tid & 3) * 16;  // 0,16,32,48

    for (int t = 0; t < SS / 32; t++) {
        __syncthreads();
        {
            const float* kp = kbase + (size_t)(t * 32 + lj) * NQKV + lc;
            const float* vp = vbase + (size_t)(t * 32 + lj) * NQKV + lc;
#pragma unroll
            for (int i = 0; i < 4; i++) {
                *(float4*)&Ks[lj][lc + i * 4] = *(const float4*)(kp + i * 4);
                *(float4*)&Vs[lj][lc + i * 4] = *(const float4*)(vp + i * 4);
            }
        }
        __syncthreads();

#pragma unroll
        for (int jc = 0; jc < 32; jc += 16) {
            float s[16];
            float mt = m;
#pragma unroll
            for (int jj = 0; jj < 16; jj++) {
                int j = jc + jj;
                float4 a = make_float4(0.f, 0.f, 0.f, 0.f);
#pragma unroll
                for (int i = 0; i < 16; i++) {
                    float4 kk = *(const float4*)&Ks[j][i * 4];
                    a.x = fmaf(q[i].x, kk.x, a.x);
                    a.y = fmaf(q[i].y, kk.y, a.y);
                    a.z = fmaf(q[i].z, kk.z, a.z);
                    a.w = fmaf(q[i].w, kk.w, a.w);
                }
                float sj = (a.x + a.y) + (a.z + a.w);
                s[jj] = sj;
                mt = fmaxf(mt, sj);
            }
            float corr = __expf(m - mt);
            m = mt;
            l *= corr;
#pragma unroll
            for (int i = 0; i < 16; i++) {
                o[i].x *= corr; o[i].y *= corr; o[i].z *= corr; o[i].w *= corr;
            }
#pragma unroll
            for (int jj = 0; jj < 16; jj++) {
                float p = __expf(s[jj] - mt);
                l += p;
                int j = jc + jj;
#pragma unroll
                for (int i = 0; i < 16; i++) {
                    float4 vv = *(const float4*)&Vs[j][i * 4];
                    o[i].x = fmaf(p, vv.x, o[i].x);
                    o[i].y = fmaf(p, vv.y, o[i].y);
                    o[i].z = fmaf(p, vv.z, o[i].z);
                    o[i].w = fmaf(p, vv.w, o[i].w);
                }
            }
        }
    }

    float inv = 1.f / l;
    float* optr = g_ctx + (size_t)(b * SS + qrow) * CD + h * DD;
#pragma unroll
    for (int i = 0; i < 16; i++) {
        float4 w = o[i];
        w.x *= inv; w.y *= inv; w.z *= inv; w.w *= inv;
        *(float4*)(optr + i * 4) = w;
    }
}

// ---------------------------------------------------------------------------
// Launch
// ---------------------------------------------------------------------------
extern "C" void kernel_launch(void* const* d_in, const int* in_sizes, int n_in,
                              void* d_out, int out_size) {
    const float* x  = (const float*)d_in[0];
    const float* Wq = (const float*)d_in[1];
    const float* Wk = (const float*)d_in[2];
    const float* Wv = (const float*)d_in[3];
    const float* Wo = (const float*)d_in[4];
    const float* bo = (const float*)d_in[5];
    const float* Aq = (const float*)d_in[6];
    const float* Bq = (const float*)d_in[7];
    const float* Ak = (const float*)d_in[8];
    const float* Bk = (const float*)d_in[9];
    const float* Av = (const float*)d_in[10];
    const float* Bv = (const float*)d_in[11];
    const float* Ao = (const float*)d_in[12];
    const float* Bo = (const float*)d_in[13];

    static float *p_Wqkv = nullptr, *p_Wo = nullptr, *p_qkv = nullptr, *p_ctx = nullptr;
    if (!p_Wqkv) {
        cudaGetSymbolAddress((void**)&p_Wqkv, g_Wqkv);
        cudaGetSymbolAddress((void**)&p_Wo,   g_Wo);
        cudaGetSymbolAddress((void**)&p_qkv,  g_qkv);
        cudaGetSymbolAddress((void**)&p_ctx,  g_ctx);
    }

    // 1) fold LoRA into weights
    fold_qkv_kernel<<<(NQKV * CD + 255) / 256, 256>>>(Wq, Wk, Wv, Aq, Bq, Ak, Bk, Av, Bv);
    fold_o_kernel<<<(CD * CD + 255) / 256, 256>>>(Wo, Ao, Bo);

    // 2) fused QKV projection: [4096 x 1280] @ [3840 x 1280]^T -> [4096 x 3840]
    sgemm_nt_kernel<false><<<dim3(NQKV / 128, MM / 128), 256>>>(x, p_Wqkv, p_qkv, CD, NQKV, nullptr);

    // 3) flash attention -> ctx [4096 x 1280]
    attn_kernel<<<dim3(SS / 128, HH, BB), 128>>>();

    // 4) output projection + bias -> d_out
    sgemm_nt_kernel<true><<<dim3(CD / 128, MM / 128), 256>>>(p_ctx, p_Wo, (float*)d_out, CD, CD, bo);
}

// round 3
// speedup vs baseline: 3.0482x; 3.0482x over previous
#include <cuda_runtime.h>
#include <cuda_bf16.h>
#include <cstdint>

#define CD 1280
#define RD 4
#define BB 2
#define SS 2048
#define MM 4096
#define HH 20
#define DD 64
#define NQKV 3840

// ---------------- device scratch (bf16 hi/lo split operands) ----------------
__device__ __nv_bfloat16 g_x_h[MM * CD],    g_x_l[MM * CD];
__device__ __nv_bfloat16 g_W_h[NQKV * CD],  g_W_l[NQKV * CD];
__device__ __nv_bfloat16 g_Wo_h[CD * CD],   g_Wo_l[CD * CD];
__device__ __nv_bfloat16 g_qkv_h[MM * NQKV], g_qkv_l[MM * NQKV];
__device__ __nv_bfloat16 g_ctx_h[MM * CD],  g_ctx_l[MM * CD];

// ---------------- helpers ----------------
__device__ __forceinline__ uint32_t smem_u32(const void* p) {
    uint32_t a;
    asm("{ .reg .u64 t; cvta.to.shared.u64 t, %1; cvt.u32.u64 %0, t; }" : "=r"(a) : "l"(p));
    return a;
}
// pack {lo, hi} floats -> bf16x2 (lo in bits [15:0])
__device__ __forceinline__ uint32_t packbf(float lo, float hi) {
    uint32_t r;
    asm("cvt.rn.bf16x2.f32 %0, %1, %2;" : "=r"(r) : "f"(hi), "f"(lo));
    return r;
}
// split pair (x,y) into hi bf16x2 and residual-lo bf16x2
__device__ __forceinline__ void split2(float x, float y, uint32_t& h, uint32_t& l) {
    __nv_bfloat16 hx = __float2bfloat16_rn(x), hy = __float2bfloat16_rn(y);
    h = ((uint32_t)__bfloat16_as_ushort(hy) << 16) | (uint32_t)__bfloat16_as_ushort(hx);
    l = packbf(x - __bfloat162float(hx), y - __bfloat162float(hy));
}

__device__ __forceinline__ void mma16816(float* d, const uint32_t* a, const uint32_t* b) {
    asm volatile(
        "mma.sync.aligned.m16n8k16.row.col.f32.bf16.bf16.f32 "
        "{%0,%1,%2,%3}, {%4,%5,%6,%7}, {%8,%9}, {%0,%1,%2,%3};"
        : "+f"(d[0]), "+f"(d[1]), "+f"(d[2]), "+f"(d[3])
        : "r"(a[0]), "r"(a[1]), "r"(a[2]), "r"(a[3]), "r"(b[0]), "r"(b[1]));
}
__device__ __forceinline__ void ldm_x4(uint32_t* r, uint32_t addr) {
    asm volatile("ldmatrix.sync.aligned.m8n8.x4.shared.b16 {%0,%1,%2,%3}, [%4];"
                 : "=r"(r[0]), "=r"(r[1]), "=r"(r[2]), "=r"(r[3]) : "r"(addr));
}
__device__ __forceinline__ void ldm_x4t(uint32_t* r, uint32_t addr) {
    asm volatile("ldmatrix.sync.aligned.m8n8.x4.trans.shared.b16 {%0,%1,%2,%3}, [%4];"
                 : "=r"(r[0]), "=r"(r[1]), "=r"(r[2]), "=r"(r[3]) : "r"(addr));
}
__device__ __forceinline__ void cpasync16(uint32_t dst, const void* src) {
    asm volatile("cp.async.cg.shared.global [%0], [%1], 16;" :: "r"(dst), "l"(src));
}
#define CP_COMMIT() asm volatile("cp.async.commit_group;" ::: "memory")
#define CP_WAIT1()  asm volatile("cp.async.wait_group 1;" ::: "memory")
#define CP_WAIT0()  asm volatile("cp.async.wait_group 0;" ::: "memory")

// ---------------------------------------------------------------------------
// Fold LoRA into weights, emit bf16 hi/lo split
// ---------------------------------------------------------------------------
__global__ void fold_qkv_kernel(const float* __restrict__ Wq, const float* __restrict__ Wk,
                                const float* __restrict__ Wv,
                                const float* __restrict__ Aq, const float* __restrict__ Bq,
                                const float* __restrict__ Ak, const float* __restrict__ Bk,
                                const float* __restrict__ Av, const float* __restrict__ Bv) {
    int idx = blockIdx.x * blockDim.x + threadIdx.x;
    if (idx >= NQKV * CD) return;
    int n = idx / CD;
    int c = idx - n * CD;
    const float *W, *A, *B;
    int j;
    if (n < CD)          { W = Wq; A = Aq; B = Bq; j = n; }
    else if (n < 2 * CD) { W = Wk; A = Ak; B = Bk; j = n - CD; }
    else                 { W = Wv; A = Av; B = Bv; j = n - 2 * CD; }
    float acc = W[j * CD + c];
#pragma unroll
    for (int r = 0; r < RD; r++)
        acc = fmaf(B[j * RD + r], A[r * CD + c], acc);
    __nv_bfloat16 h = __float2bfloat16_rn(acc);
    g_W_h[idx] = h;
    g_W_l[idx] = __float2bfloat16_rn(acc - __bfloat162float(h));
}

__global__ void fold_o_kernel(const float* __restrict__ Wo,
                              const float* __restrict__ Ao, const float* __restrict__ Bo) {
    int idx = blockIdx.x * blockDim.x + threadIdx.x;
    if (idx >= CD * CD) return;
    int j = idx / CD;
    int c = idx - j * CD;
    float acc = Wo[idx];
#pragma unroll
    for (int r = 0; r < RD; r++)
        acc = fmaf(Bo[j * RD + r], Ao[r * CD + c], acc);
    __nv_bfloat16 h = __float2bfloat16_rn(acc);
    g_Wo_h[idx] = h;
    g_Wo_l[idx] = __float2bfloat16_rn(acc - __bfloat162float(h));
}

__global__ void convert_x_kernel(const float* __restrict__ x) {
    int idx = blockIdx.x * blockDim.x + threadIdx.x;
    if (idx >= MM * CD) return;
    float v = x[idx];
    __nv_bfloat16 h = __float2bfloat16_rn(v);
    g_x_h[idx] = h;
    g_x_l[idx] = __float2bfloat16_rn(v - __bfloat162float(h));
}

// ---------------------------------------------------------------------------
// HMMA GEMM:  C[m][n] = sum_k A[m][k]*B[n][k]  (split-bf16 x3)
// BM=128, BN=128, BK=32, 256 thr (8 warps: wm=wid&1 -> 64 rows, wn=wid>>1 -> 32 cols)
// smem rows padded to 80B for conflict-free ldmatrix. cp.async 2-stage.
// OUTMODE 0: write bf16 hi/lo;  OUTMODE 1: write fp32 + bias.
// ---------------------------------------------------------------------------
#define GARR 10240                      // bytes per operand array per stage (128*80)
#define GSTG (4 * GARR)                 // 40960
#define GEMM_SMEM (2 * GSTG)            // 81920

template <int OUTMODE>
__global__ __launch_bounds__(256, 1)
void gemm_tc(const __nv_bfloat16* __restrict__ Ah, const __nv_bfloat16* __restrict__ Al,
             const __nv_bfloat16* __restrict__ Bh, const __nv_bfloat16* __restrict__ Bl,
             float* __restrict__ Cf, __nv_bfloat16* __restrict__ Ch, __nv_bfloat16* __restrict__ Cl,
             int K, int N, const float* __restrict__ bias) {
    extern __shared__ char smem[];
    const uint32_t sb = smem_u32(smem);
    const int tid = threadIdx.x, lane = tid & 31, wid = tid >> 5;
    const int wm = wid & 1, wn = wid >> 1;
    const int bRow = blockIdx.y * 128, bCol = blockIdx.x * 128;

    float acc[4][4][4];
#pragma unroll
    for (int i = 0; i < 4; i++)
#pragma unroll
        for (int j = 0; j < 4; j++)
#pragma unroll
            for (int e = 0; e < 4; e++) acc[i][j][e] = 0.f;

    const int NIT = K / 32;
    const int row0 = tid >> 2, ch0 = tid & 3;          // task 0
    const int row1 = (tid + 256) >> 2, ch1 = tid & 3;  // task 1 (ch same: (tid+256)&3==tid&3)

    // issue one stage of cp.async loads
    auto issue = [&](int it, int s) {
        const __nv_bfloat16* srcs[4] = {Ah, Al, Bh, Bl};
#pragma unroll
        for (int a = 0; a < 4; a++) {
            const int rb = (a < 2) ? bRow : bCol;
            const uint32_t dst = sb + s * GSTG + a * GARR;
            cpasync16(dst + row0 * 80 + ch0 * 16,
                      srcs[a] + (size_t)(rb + row0) * K + it * 32 + ch0 * 8);
            cpasync16(dst + row1 * 80 + ch1 * 16,
                      srcs[a] + (size_t)(rb + row1) * K + it * 32 + ch1 * 8);
        }
        CP_COMMIT();
    };

    issue(0, 0);
    const int g01 = (lane >> 3) & 1, g23 = lane >> 4, l7 = lane & 7;

    for (int i = 0; i < NIT; i++) {
        if (i + 1 < NIT) { issue(i + 1, (i + 1) & 1); CP_WAIT1(); }
        else             { CP_WAIT0(); }
        __syncthreads();
        const uint32_t aH = sb + (i & 1) * GSTG;
        const uint32_t aL = aH + GARR;
        const uint32_t bH = aH + 2 * GARR;
        const uint32_t bL = aH + 3 * GARR;
#pragma unroll
        for (int k0 = 0; k0 < 32; k0 += 16) {
            uint32_t ah[4][4], al[4][4], bh[4][2], bl[4][2];
#pragma unroll
            for (int mt = 0; mt < 4; mt++) {
                uint32_t ad = aH + (uint32_t)(wm * 64 + mt * 16 + l7 + g01 * 8) * 80 + (k0 + g23 * 8) * 2;
                ldm_x4(ah[mt], ad);
                ldm_x4(al[mt], ad + GARR);
            }
#pragma unroll
            for (int p = 0; p < 2; p++) {
                uint32_t bt[4], bt2[4];
                uint32_t bd = bH + (uint32_t)(wn * 32 + p * 16 + l7 + g23 * 8) * 80 + (k0 + g01 * 8) * 2;
                ldm_x4(bt, bd);
                ldm_x4(bt2, bd + GARR);
                bh[2 * p][0] = bt[0]; bh[2 * p][1] = bt[1];
                bh[2 * p + 1][0] = bt[2]; bh[2 * p + 1][1] = bt[3];
                bl[2 * p][0] = bt2[0]; bl[2 * p][1] = bt2[1];
                bl[2 * p + 1][0] = bt2[2]; bl[2 * p + 1][1] = bt2[3];
            }
#pragma unroll
            for (int mt = 0; mt < 4; mt++)
#pragma unroll
                for (int nt = 0; nt < 4; nt++) {
                    mma16816(acc[mt][nt], ah[mt], bh[nt]);
                    mma16816(acc[mt][nt], ah[mt], bl[nt]);
                    mma16816(acc[mt][nt], al[mt], bh[nt]);
                }
        }
        __syncthreads();
    }

    // epilogue
    const int rq = lane >> 2, cq = (lane & 3) * 2;
#pragma unroll
    for (int mt = 0; mt < 4; mt++) {
#pragma unroll
        for (int nt = 0; nt < 4; nt++) {
            int r = bRow + wm * 64 + mt * 16 + rq;
            int c = bCol + wn * 32 + nt * 8 + cq;
            if (OUTMODE == 1) {
                float b0 = bias[c], b1 = bias[c + 1];
                *(float2*)(Cf + (size_t)r * N + c) =
                    make_float2(acc[mt][nt][0] + b0, acc[mt][nt][1] + b1);
                *(float2*)(Cf + (size_t)(r + 8) * N + c) =
                    make_float2(acc[mt][nt][2] + b0, acc[mt][nt][3] + b1);
            } else {
                uint32_t h0, l0, h1, l1;
                split2(acc[mt][nt][0], acc[mt][nt][1], h0, l0);
                split2(acc[mt][nt][2], acc[mt][nt][3], h1, l1);
                *(uint32_t*)(Ch + (size_t)r * N + c) = h0;
                *(uint32_t*)(Cl + (size_t)r * N + c) = l0;
                *(uint32_t*)(Ch + (size_t)(r + 8) * N + c) = h1;
                *(uint32_t*)(Cl + (size_t)(r + 8) * N + c) = l1;
            }
        }
    }
}

// ---------------------------------------------------------------------------
// Tensor-core flash attention (split-bf16 x3).
// Block: 256 thr (8 warps), Br=128 q-rows (warp w -> m16 tile), Bc=64 kv tiles.
// K/V hi/lo in smem (row stride 144B, ldmatrix conflict-free), cp.async 2-stage.
// ---------------------------------------------------------------------------
#define AARR 9216                        // bytes per K/V array (64 rows * 144B)
#define ASTG (4 * AARR)                  // 36864
#define ATTN_SMEM (2 * ASTG)             // 73728

__global__ __launch_bounds__(256, 1)
void attn_tc() {
    extern __shared__ char smem[];
    const uint32_t sb = smem_u32(smem);
    const int tid = threadIdx.x, lane = tid & 31, wid = tid >> 5;
    const int b = blockIdx.z, h = blockIdx.y, qb = blockIdx.x;
    const int rq = lane >> 2, cq = (lane & 3) * 2;
    const int l7 = lane & 7, g01 = (lane >> 3) & 1, g23 = lane >> 4;

    // ---- Q fragments (hi/lo), loaded once directly from gmem ----
    uint32_t qh[16], ql[16];
    {
        const size_t base = (size_t)(b * SS + qb * 128 + wid * 16 + rq) * NQKV + h * DD;
#pragma unroll
        for (int kt = 0; kt < 4; kt++) {
            int c = kt * 16 + cq;
            qh[kt * 4 + 0] = *(const uint32_t*)(g_qkv_h + base + c);
            qh[kt * 4 + 1] = *(const uint32_t*)(g_qkv_h + base + (size_t)8 * NQKV + c);
            qh[kt * 4 + 2] = *(const uint32_t*)(g_qkv_h + base + c + 8);
            qh[kt * 4 + 3] = *(const uint32_t*)(g_qkv_h + base + (size_t)8 * NQKV + c + 8);
            ql[kt * 4 + 0] = *(const uint32_t*)(g_qkv_l + base + c);
            ql[kt * 4 + 1] = *(const uint32_t*)(g_qkv_l + base + (size_t)8 * NQKV + c);
            ql[kt * 4 + 2] = *(const uint32_t*)(g_qkv_l + base + c + 8);
            ql[kt * 4 + 3] = *(const uint32_t*)(g_qkv_l + base + (size_t)8 * NQKV + c + 8);
        }
    }

    float O[8][4];
#pragma unroll
    for (int i = 0; i < 8; i++)
#pragma unroll
        for (int e = 0; e < 4; e++) O[i][e] = 0.f;
    float m0 = -1e30f, m1 = -1e30f, sl0 = 0.f, sl1 = 0.f;

    // K/V loader: arrays {Kh, Kl, Vh, Vl}; 512 chunks each -> 2 per thread per array
    const int lrow0 = tid >> 3, lch0 = tid & 7;
    const int lrow1 = (tid + 256) >> 3;
    auto issue = [&](int it, int s) {
        const __nv_bfloat16* srcs[4] = {g_qkv_h, g_qkv_l, g_qkv_h, g_qkv_l};
        const int cbase[4] = {CD + h * DD, CD + h * DD, 2 * CD + h * DD, 2 * CD + h * DD};
#pragma unroll
        for (int a = 0; a < 4; a++) {
            const uint32_t dst = sb + s * ASTG + a * AARR;
            cpasync16(dst + lrow0 * 144 + lch0 * 16,
                      srcs[a] + (size_t)(b * SS + it * 64 + lrow0) * NQKV + cbase[a] + lch0 * 8);
            cpasync16(dst + lrow1 * 144 + lch0 * 16,
                      srcs[a] + (size_t)(b * SS + it * 64 + lrow1) * NQKV + cbase[a] + lch0 * 8);
        }
        CP_COMMIT();
    };

    issue(0, 0);
    const int NIT = SS / 64;
    for (int i = 0; i < NIT; i++) {
        if (i + 1 < NIT) { issue(i + 1, (i + 1) & 1); CP_WAIT1(); }
        else             { CP_WAIT0(); }
        __syncthreads();
        const uint32_t kH = sb + (i & 1) * ASTG;
        const uint32_t kL = kH + AARR;
        const uint32_t vH = kH + 2 * AARR;
        const uint32_t vL = kH + 3 * AARR;

        // ---- S = Q K^T (x3 passes) ----
        float S[8][4];
#pragma unroll
        for (int j = 0; j < 8; j++)
#pragma unroll
            for (int e = 0; e < 4; e++) S[j][e] = 0.f;
#pragma unroll
        for (int kt = 0; kt < 4; kt++) {
#pragma unroll
            for (int p = 0; p < 4; p++) {
                uint32_t kh4[4], kl4[4];
                uint32_t kd = kH + (uint32_t)(p * 16 + l7 + g23 * 8) * 144 + (kt * 16 + g01 * 8) * 2;
                ldm_x4(kh4, kd);
                ldm_x4(kl4, kd + AARR);
                mma16816(S[2 * p],     &qh[kt * 4], &kh4[0]);
                mma16816(S[2 * p],     &qh[kt * 4], &kl4[0]);
                mma16816(S[2 * p],     &ql[kt * 4], &kh4[0]);
                mma16816(S[2 * p + 1], &qh[kt * 4], &kh4[2]);
                mma16816(S[2 * p + 1], &qh[kt * 4], &kl4[2]);
                mma16816(S[2 * p + 1], &ql[kt * 4], &kh4[2]);
            }
        }

        // ---- online softmax (rows rq and rq+8, quad-wide reduce) ----
        float nm0 = m0, nm1 = m1;
#pragma unroll
        for (int j = 0; j < 8; j++) {
            S[j][0] *= 0.125f; S[j][1] *= 0.125f; S[j][2] *= 0.125f; S[j][3] *= 0.125f;
            nm0 = fmaxf(nm0, fmaxf(S[j][0], S[j][1]));
            nm1 = fmaxf(nm1, fmaxf(S[j][2], S[j][3]));
        }
        nm0 = fmaxf(nm0, __shfl_xor_sync(0xffffffff, nm0, 1));
        nm0 = fmaxf(nm0, __shfl_xor_sync(0xffffffff, nm0, 2));
        nm1 = fmaxf(nm1, __shfl_xor_sync(0xffffffff, nm1, 1));
        nm1 = fmaxf(nm1, __shfl_xor_sync(0xffffffff, nm1, 2));
        float c0 = __expf(m0 - nm0), c1 = __expf(m1 - nm1);
        m0 = nm0; m1 = nm1;
        float s0 = 0.f, s1 = 0.f;
#pragma unroll
        for (int j = 0; j < 8; j++) {
            S[j][0] = __expf(S[j][0] - m0); S[j][1] = __expf(S[j][1] - m0);
            S[j][2] = __expf(S[j][2] - m1); S[j][3] = __expf(S[j][3] - m1);
            s0 += S[j][0] + S[j][1];
            s1 += S[j][2] + S[j][3];
        }
        s0 += __shfl_xor_sync(0xffffffff, s0, 1);
        s0 += __shfl_xor_sync(0xffffffff, s0, 2);
        s1 += __shfl_xor_sync(0xffffffff, s1, 1);
        s1 += __shfl_xor_sync(0xffffffff, s1, 2);
        sl0 = sl0 * c0 + s0;
        sl1 = sl1 * c1 + s1;
#pragma unroll
        for (int nt = 0; nt < 8; nt++) {
            O[nt][0] *= c0; O[nt][1] *= c0; O[nt][2] *= c1; O[nt][3] *= c1;
        }

        // ---- O += P V (x3 passes) ----
#pragma unroll
        for (int kt = 0; kt < 4; kt++) {
            uint32_t ph[4], pl[4];
            split2(S[2 * kt][0],     S[2 * kt][1],     ph[0], pl[0]);
            split2(S[2 * kt][2],     S[2 * kt][3],     ph[1], pl[1]);
            split2(S[2 * kt + 1][0], S[2 * kt + 1][1], ph[2], pl[2]);
            split2(S[2 * kt + 1][2], S[2 * kt + 1][3], ph[3], pl[3]);
#pragma unroll
            for (int p = 0; p < 4; p++) {
                uint32_t vh4[4], vl4[4];
                uint32_t vd = vH + (uint32_t)(kt * 16 + l7 + g01 * 8) * 144 + (p * 16 + g23 * 8) * 2;
                ldm_x4t(vh4, vd);
                ldm_x4t(vl4, vd + AARR);
                mma16816(O[2 * p],     ph, &vh4[0]);
                mma16816(O[2 * p],     ph, &vl4[0]);
                mma16816(O[2 * p],     pl, &vh4[0]);
                mma16816(O[2 * p + 1], ph, &vh4[2]);
                mma16816(O[2 * p + 1], ph, &vl4[2]);
                mma16816(O[2 * p + 1], pl, &vh4[2]);
            }
        }
        __syncthreads();
    }

    // ---- store ctx as bf16 hi/lo ----
    const float i0 = 1.f / sl0, i1 = 1.f / sl1;
    const size_t rb0 = (size_t)(b * SS + qb * 128 + wid * 16 + rq) * CD + h * DD;
    const size_t rb1 = rb0 + (size_t)8 * CD;
#pragma unroll
    for (int nt = 0; nt < 8; nt++) {
        int c = nt * 8 + cq;
        uint32_t h0, l0, h1, l1;
        split2(O[nt][0] * i0, O[nt][1] * i0, h0, l0);
        split2(O[nt][2] * i1, O[nt][3] * i1, h1, l1);
        *(uint32_t*)(g_ctx_h + rb0 + c) = h0;
        *(uint32_t*)(g_ctx_l + rb0 + c) = l0;
        *(uint32_t*)(g_ctx_h + rb1 + c) = h1;
        *(uint32_t*)(g_ctx_l + rb1 + c) = l1;
    }
}

// ---------------------------------------------------------------------------
// Launch
// ---------------------------------------------------------------------------
extern "C" void kernel_launch(void* const* d_in, const int* in_sizes, int n_in,
                              void* d_out, int out_size) {
    const float* x  = (const float*)d_in[0];
    const float* Wq = (const float*)d_in[1];
    const float* Wk = (const float*)d_in[2];
    const float* Wv = (const float*)d_in[3];
    const float* Wo = (const float*)d_in[4];
    const float* bo = (const float*)d_in[5];
    const float* Aq = (const float*)d_in[6];
    const float* Bq = (const float*)d_in[7];
    const float* Ak = (const float*)d_in[8];
    const float* Bk = (const float*)d_in[9];
    const float* Av = (const float*)d_in[10];
    const float* Bv = (const float*)d_in[11];
    const float* Ao = (const float*)d_in[12];
    const float* Bo = (const float*)d_in[13];

    static __nv_bfloat16 *p_xh, *p_xl, *p_Wh, *p_Wl, *p_Woh, *p_Wol, *p_qh, *p_ql, *p_ch, *p_cl;
    static bool init = false;
    if (!init) {
        cudaGetSymbolAddress((void**)&p_xh, g_x_h);
        cudaGetSymbolAddress((void**)&p_xl, g_x_l);
        cudaGetSymbolAddress((void**)&p_Wh, g_W_h);
        cudaGetSymbolAddress((void**)&p_Wl, g_W_l);
        cudaGetSymbolAddress((void**)&p_Woh, g_Wo_h);
        cudaGetSymbolAddress((void**)&p_Wol, g_Wo_l);
        cudaGetSymbolAddress((void**)&p_qh, g_qkv_h);
        cudaGetSymbolAddress((void**)&p_ql, g_qkv_l);
        cudaGetSymbolAddress((void**)&p_ch, g_ctx_h);
        cudaGetSymbolAddress((void**)&p_cl, g_ctx_l);
        cudaFuncSetAttribute(gemm_tc<0>, cudaFuncAttributeMaxDynamicSharedMemorySize, GEMM_SMEM);
        cudaFuncSetAttribute(gemm_tc<1>, cudaFuncAttributeMaxDynamicSharedMemorySize, GEMM_SMEM);
        cudaFuncSetAttribute(attn_tc, cudaFuncAttributeMaxDynamicSharedMemorySize, ATTN_SMEM);
        init = true;
    }

    // 1) fold + split
    fold_qkv_kernel<<<(NQKV * CD + 255) / 256, 256>>>(Wq, Wk, Wv, Aq, Bq, Ak, Bk, Av, Bv);
    fold_o_kernel<<<(CD * CD + 255) / 256, 256>>>(Wo, Ao, Bo);
    convert_x_kernel<<<(MM * CD + 255) / 256, 256>>>(x);

    // 2) QKV projection -> g_qkv hi/lo
    gemm_tc<0><<<dim3(NQKV / 128, MM / 128), 256, GEMM_SMEM>>>(
        p_xh, p_xl, p_Wh, p_Wl, nullptr, p_qh, p_ql, CD, NQKV, nullptr);

    // 3) attention -> g_ctx hi/lo
    attn_tc<<<dim3(SS / 128, HH, BB), 256, ATTN_SMEM>>>();

    // 4) O projection + bias -> d_out (fp32)
    gemm_tc<1><<<dim3(CD / 128, MM / 128), 256, GEMM_SMEM>>>(
        p_ch, p_cl, p_Woh, p_Wol, (float*)d_out, nullptr, nullptr, CD, CD, bo);
}

// round 5
// speedup vs baseline: 3.2984x; 1.0821x over previous
#include <cuda_runtime.h>
#include <cuda_bf16.h>
#include <cstdint>

#define CD 1280
#define RD 4
#define BB 2
#define SS 2048
#define MM 4096
#define HH 20
#define DD 64
#define NQKV 3840

// ---------------- device scratch (bf16 hi/lo split operands) ----------------
__device__ __nv_bfloat16 g_x_h[MM * CD],    g_x_l[MM * CD];
__device__ __nv_bfloat16 g_W_h[NQKV * CD],  g_W_l[NQKV * CD];
__device__ __nv_bfloat16 g_Wo_h[CD * CD],   g_Wo_l[CD * CD];
__device__ __nv_bfloat16 g_qkv_h[MM * NQKV], g_qkv_l[MM * NQKV];
__device__ __nv_bfloat16 g_ctx_h[MM * CD],  g_ctx_l[MM * CD];

// ---------------- helpers ----------------
__device__ __forceinline__ uint32_t smem_u32(const void* p) {
    uint32_t a;
    asm("{ .reg .u64 t; cvta.to.shared.u64 t, %1; cvt.u32.u64 %0, t; }" : "=r"(a) : "l"(p));
    return a;
}
__device__ __forceinline__ uint32_t packbf(float lo, float hi) {
    uint32_t r;
    asm("cvt.rn.bf16x2.f32 %0, %1, %2;" : "=r"(r) : "f"(hi), "f"(lo));
    return r;
}
__device__ __forceinline__ void split2(float x, float y, uint32_t& h, uint32_t& l) {
    __nv_bfloat16 hx = __float2bfloat16_rn(x), hy = __float2bfloat16_rn(y);
    h = ((uint32_t)__bfloat16_as_ushort(hy) << 16) | (uint32_t)__bfloat16_as_ushort(hx);
    l = packbf(x - __bfloat162float(hx), y - __bfloat162float(hy));
}

__device__ __forceinline__ void mma16816(float* d, const uint32_t* a, const uint32_t* b) {
    asm volatile(
        "mma.sync.aligned.m16n8k16.row.col.f32.bf16.bf16.f32 "
        "{%0,%1,%2,%3}, {%4,%5,%6,%7}, {%8,%9}, {%0,%1,%2,%3};"
        : "+f"(d[0]), "+f"(d[1]), "+f"(d[2]), "+f"(d[3])
        : "r"(a[0]), "r"(a[1]), "r"(a[2]), "r"(a[3]), "r"(b[0]), "r"(b[1]));
}
__device__ __forceinline__ void ldm_x4(uint32_t* r, uint32_t addr) {
    asm volatile("ldmatrix.sync.aligned.m8n8.x4.shared.b16 {%0,%1,%2,%3}, [%4];"
                 : "=r"(r[0]), "=r"(r[1]), "=r"(r[2]), "=r"(r[3]) : "r"(addr));
}
__device__ __forceinline__ void ldm_x4t(uint32_t* r, uint32_t addr) {
    asm volatile("ldmatrix.sync.aligned.m8n8.x4.trans.shared.b16 {%0,%1,%2,%3}, [%4];"
                 : "=r"(r[0]), "=r"(r[1]), "=r"(r[2]), "=r"(r[3]) : "r"(addr));
}
__device__ __forceinline__ void cpasync16(uint32_t dst, const void* src) {
    asm volatile("cp.async.cg.shared.global [%0], [%1], 16;" :: "r"(dst), "l"(src));
}
#define CP_COMMIT() asm volatile("cp.async.commit_group;" ::: "memory")
#define CP_WAIT1()  asm volatile("cp.async.wait_group 1;" ::: "memory")
#define CP_WAIT0()  asm volatile("cp.async.wait_group 0;" ::: "memory")

// ---------------------------------------------------------------------------
// Fold LoRA into weights, emit bf16 hi/lo split
// ---------------------------------------------------------------------------
__global__ void fold_qkv_kernel(const float* __restrict__ Wq, const float* __restrict__ Wk,
                                const float* __restrict__ Wv,
                                const float* __restrict__ Aq, const float* __restrict__ Bq,
                                const float* __restrict__ Ak, const float* __restrict__ Bk,
                                const float* __restrict__ Av, const float* __restrict__ Bv) {
    int idx = blockIdx.x * blockDim.x + threadIdx.x;
    if (idx >= NQKV * CD) return;
    int n = idx / CD;
    int c = idx - n * CD;
    const float *W, *A, *B;
    int j;
    if (n < CD)          { W = Wq; A = Aq; B = Bq; j = n; }
    else if (n < 2 * CD) { W = Wk; A = Ak; B = Bk; j = n - CD; }
    else                 { W = Wv; A = Av; B = Bv; j = n - 2 * CD; }
    float acc = W[j * CD + c];
#pragma unroll
    for (int r = 0; r < RD; r++)
        acc = fmaf(B[j * RD + r], A[r * CD + c], acc);
    __nv_bfloat16 h = __float2bfloat16_rn(acc);
    g_W_h[idx] = h;
    g_W_l[idx] = __float2bfloat16_rn(acc - __bfloat162float(h));
}

__global__ void fold_o_kernel(const float* __restrict__ Wo,
                              const float* __restrict__ Ao, const float* __restrict__ Bo) {
    int idx = blockIdx.x * blockDim.x + threadIdx.x;
    if (idx >= CD * CD) return;
    int j = idx / CD;
    int c = idx - j * CD;
    float acc = Wo[idx];
#pragma unroll
    for (int r = 0; r < RD; r++)
        acc = fmaf(Bo[j * RD + r], Ao[r * CD + c], acc);
    __nv_bfloat16 h = __float2bfloat16_rn(acc);
    g_Wo_h[idx] = h;
    g_Wo_l[idx] = __float2bfloat16_rn(acc - __bfloat162float(h));
}

__global__ void convert_x_kernel(const float* __restrict__ x) {
    int idx = blockIdx.x * blockDim.x + threadIdx.x;
    if (idx >= MM * CD) return;
    float v = x[idx];
    __nv_bfloat16 h = __float2bfloat16_rn(v);
    g_x_h[idx] = h;
    g_x_l[idx] = __float2bfloat16_rn(v - __bfloat162float(h));
}

// ---------------------------------------------------------------------------
// HMMA GEMM:  C[m][n] = sum_k A[m][k]*B[n][k]  (split-bf16 x3)
// BM=128, BN=128, BK=32, 256 thr, 2 CTAs/SM (128-reg budget).
// Fragment pressure minimized: B hi+lo per k-half (16 regs), A hi+lo per mt (8).
// ---------------------------------------------------------------------------
#define GARR 10240
#define GSTG (4 * GARR)
#define GEMM_SMEM (2 * GSTG)            // 81920

template <int OUTMODE>
__global__ __launch_bounds__(256, 2)
void gemm_tc(const __nv_bfloat16* __restrict__ Ah, const __nv_bfloat16* __restrict__ Al,
             const __nv_bfloat16* __restrict__ Bh, const __nv_bfloat16* __restrict__ Bl,
             float* __restrict__ Cf, __nv_bfloat16* __restrict__ Ch, __nv_bfloat16* __restrict__ Cl,
             int K, int N, const float* __restrict__ bias) {
    extern __shared__ char smem[];
    const uint32_t sb = smem_u32(smem);
    const int tid = threadIdx.x, lane = tid & 31, wid = tid >> 5;
    const int wm = wid & 1, wn = wid >> 1;
    const int bRow = blockIdx.y * 128, bCol = blockIdx.x * 128;

    float acc[4][4][4];
#pragma unroll
    for (int i = 0; i < 4; i++)
#pragma unroll
        for (int j = 0; j < 4; j++)
#pragma unroll
            for (int e = 0; e < 4; e++) acc[i][j][e] = 0.f;

    const int NIT = K / 32;
    const int row0 = tid >> 2, ch0 = tid & 3;
    const int row1 = (tid + 256) >> 2;

    auto issue = [&](int it, int s) {
        const uint32_t dst = sb + s * GSTG;
        const size_t ko = (size_t)it * 32 + ch0 * 8;
        cpasync16(dst + 0 * GARR + row0 * 80 + ch0 * 16, Ah + (size_t)(bRow + row0) * K + ko);
        cpasync16(dst + 0 * GARR + row1 * 80 + ch0 * 16, Ah + (size_t)(bRow + row1) * K + ko);
        cpasync16(dst + 1 * GARR + row0 * 80 + ch0 * 16, Al + (size_t)(bRow + row0) * K + ko);
        cpasync16(dst + 1 * GARR + row1 * 80 + ch0 * 16, Al + (size_t)(bRow + row1) * K + ko);
        cpasync16(dst + 2 * GARR + row0 * 80 + ch0 * 16, Bh + (size_t)(bCol + row0) * K + ko);
        cpasync16(dst + 2 * GARR + row1 * 80 + ch0 * 16, Bh + (size_t)(bCol + row1) * K + ko);
        cpasync16(dst + 3 * GARR + row0 * 80 + ch0 * 16, Bl + (size_t)(bCol + row0) * K + ko);
        cpasync16(dst + 3 * GARR + row1 * 80 + ch0 * 16, Bl + (size_t)(bCol + row1) * K + ko);
        CP_COMMIT();
    };

    issue(0, 0);
    const int g01 = (lane >> 3) & 1, g23 = lane >> 4, l7 = lane & 7;

    for (int i = 0; i < NIT; i++) {
        if (i + 1 < NIT) { issue(i + 1, (i + 1) & 1); CP_WAIT1(); }
        else             { CP_WAIT0(); }
        __syncthreads();
        const uint32_t aH = sb + (i & 1) * GSTG;
        const uint32_t bH = aH + 2 * GARR;
#pragma unroll
        for (int k0 = 0; k0 < 32; k0 += 16) {
            uint32_t bh[4][2], bl[4][2];
#pragma unroll
            for (int p = 0; p < 2; p++) {
                uint32_t bt[4], bt2[4];
                uint32_t bd = bH + (uint32_t)(wn * 32 + p * 16 + l7 + g23 * 8) * 80 + (k0 + g01 * 8) * 2;
                ldm_x4(bt, bd);
                ldm_x4(bt2, bd + GARR);
                bh[2 * p][0] = bt[0]; bh[2 * p][1] = bt[1];
                bh[2 * p + 1][0] = bt[2]; bh[2 * p + 1][1] = bt[3];
                bl[2 * p][0] = bt2[0]; bl[2 * p][1] = bt2[1];
                bl[2 * p + 1][0] = bt2[2]; bl[2 * p + 1][1] = bt2[3];
            }
#pragma unroll
            for (int mt = 0; mt < 4; mt++) {
                uint32_t ah[4], al[4];
                uint32_t ad = aH + (uint32_t)(wm * 64 + mt * 16 + l7 + g01 * 8) * 80 + (k0 + g23 * 8) * 2;
                ldm_x4(ah, ad);
                ldm_x4(al, ad + GARR);
#pragma unroll
                for (int nt = 0; nt < 4; nt++) {
                    mma16816(acc[mt][nt], ah, bh[nt]);
                    mma16816(acc[mt][nt], ah, bl[nt]);
                    mma16816(acc[mt][nt], al, bh[nt]);
                }
            }
        }
        __syncthreads();
    }

    const int rq = lane >> 2, cq = (lane & 3) * 2;
#pragma unroll
    for (int mt = 0; mt < 4; mt++) {
#pragma unroll
        for (int nt = 0; nt < 4; nt++) {
            int r = bRow + wm * 64 + mt * 16 + rq;
            int c = bCol + wn * 32 + nt * 8 + cq;
            if (OUTMODE == 1) {
                float b0 = bias[c], b1 = bias[c + 1];
                *(float2*)(Cf + (size_t)r * N + c) =
                    make_float2(acc[mt][nt][0] + b0, acc[mt][nt][1] + b1);
                *(float2*)(Cf + (size_t)(r + 8) * N + c) =
                    make_float2(acc[mt][nt][2] + b0, acc[mt][nt][3] + b1);
            } else {
                uint32_t h0, l0, h1, l1;
                split2(acc[mt][nt][0], acc[mt][nt][1], h0, l0);
                split2(acc[mt][nt][2], acc[mt][nt][3], h1, l1);
                *(uint32_t*)(Ch + (size_t)r * N + c) = h0;
                *(uint32_t*)(Cl + (size_t)r * N + c) = l0;
                *(uint32_t*)(Ch + (size_t)(r + 8) * N + c) = h1;
                *(uint32_t*)(Cl + (size_t)(r + 8) * N + c) = l1;
            }
        }
    }
}

// ---------------------------------------------------------------------------
// Tensor-core flash attention (split-bf16 x3). 256 thr, 2 CTAs/SM.
// ---------------------------------------------------------------------------
#define AARR 9216
#define ASTG (4 * AARR)
#define ATTN_SMEM (2 * ASTG)            // 73728

__global__ __launch_bounds__(256, 2)
void attn_tc() {
    extern __shared__ char smem[];
    const uint32_t sb = smem_u32(smem);
    const int tid = threadIdx.x, lane = tid & 31, wid = tid >> 5;
    const int b = blockIdx.z, h = blockIdx.y, qb = blockIdx.x;
    const int rq = lane >> 2, cq = (lane & 3) * 2;
    const int l7 = lane & 7, g01 = (lane >> 3) & 1, g23 = lane >> 4;

    uint32_t qh[16], ql[16];
    {
        const size_t base = (size_t)(b * SS + qb * 128 + wid * 16 + rq) * NQKV + h * DD;
#pragma unroll
        for (int kt = 0; kt < 4; kt++) {
            int c = kt * 16 + cq;
            qh[kt * 4 + 0] = *(const uint32_t*)(g_qkv_h + base + c);
            qh[kt * 4 + 1] = *(const uint32_t*)(g_qkv_h + base + (size_t)8 * NQKV + c);
            qh[kt * 4 + 2] = *(const uint32_t*)(g_qkv_h + base + c + 8);
            qh[kt * 4 + 3] = *(const uint32_t*)(g_qkv_h + base + (size_t)8 * NQKV + c + 8);
            ql[kt * 4 + 0] = *(const uint32_t*)(g_qkv_l + base + c);
            ql[kt * 4 + 1] = *(const uint32_t*)(g_qkv_l + base + (size_t)8 * NQKV + c);
            ql[kt * 4 + 2] = *(const uint32_t*)(g_qkv_l + base + c + 8);
            ql[kt * 4 + 3] = *(const uint32_t*)(g_qkv_l + base + (size_t)8 * NQKV + c + 8);
        }
    }

    float O[8][4];
#pragma unroll
    for (int i = 0; i < 8; i++)
#pragma unroll
        for (int e = 0; e < 4; e++) O[i][e] = 0.f;
    float m0 = -1e30f, m1 = -1e30f, sl0 = 0.f, sl1 = 0.f;

    const int lrow0 = tid >> 3, lch0 = tid & 7;
    const int lrow1 = (tid + 256) >> 3;
    auto issue = [&](int it, int s) {
        const uint32_t dst = sb + s * ASTG;
        const size_t r0 = (size_t)(b * SS + it * 64 + lrow0) * NQKV;
        const size_t r1 = (size_t)(b * SS + it * 64 + lrow1) * NQKV;
        const int kc = CD + h * DD + lch0 * 8, vc = 2 * CD + h * DD + lch0 * 8;
        cpasync16(dst + 0 * AARR + lrow0 * 144 + lch0 * 16, g_qkv_h + r0 + kc);
        cpasync16(dst + 0 * AARR + lrow1 * 144 + lch0 * 16, g_qkv_h + r1 + kc);
        cpasync16(dst + 1 * AARR + lrow0 * 144 + lch0 * 16, g_qkv_l + r0 + kc);
        cpasync16(dst + 1 * AARR + lrow1 * 144 + lch0 * 16, g_qkv_l + r1 + kc);
        cpasync16(dst + 2 * AARR + lrow0 * 144 + lch0 * 16, g_qkv_h + r0 + vc);
        cpasync16(dst + 2 * AARR + lrow1 * 144 + lch0 * 16, g_qkv_h + r1 + vc);
        cpasync16(dst + 3 * AARR + lrow0 * 144 + lch0 * 16, g_qkv_l + r0 + vc);
        cpasync16(dst + 3 * AARR + lrow1 * 144 + lch0 * 16, g_qkv_l + r1 + vc);
        CP_COMMIT();
    };

    issue(0, 0);
    const int NIT = SS / 64;
    for (int i = 0; i < NIT; i++) {
        if (i + 1 < NIT) { issue(i + 1, (i + 1) & 1); CP_WAIT1(); }
        else             { CP_WAIT0(); }
        __syncthreads();
        const uint32_t kH = sb + (i & 1) * ASTG;
        const uint32_t vH = kH + 2 * AARR;

        float S[8][4];
#pragma unroll
        for (int j = 0; j < 8; j++)
#pragma unroll
            for (int e = 0; e < 4; e++) S[j][e] = 0.f;
#pragma unroll
        for (int kt = 0; kt < 4; kt++) {
#pragma unroll
            for (int p = 0; p < 4; p++) {
                uint32_t kh4[4], kl4[4];
                uint32_t kd = kH + (uint32_t)(p * 16 + l7 + g23 * 8) * 144 + (kt * 16 + g01 * 8) * 2;
                ldm_x4(kh4, kd);
                ldm_x4(kl4, kd + AARR);
                mma16816(S[2 * p],     &qh[kt * 4], &kh4[0]);
                mma16816(S[2 * p],     &qh[kt * 4], &kl4[0]);
                mma16816(S[2 * p],     &ql[kt * 4], &kh4[0]);
                mma16816(S[2 * p + 1], &qh[kt * 4], &kh4[2]);
                mma16816(S[2 * p + 1], &qh[kt * 4], &kl4[2]);
                mma16816(S[2 * p + 1], &ql[kt * 4], &kh4[2]);
            }
        }

        float nm0 = m0, nm1 = m1;
#pragma unroll
        for (int j = 0; j < 8; j++) {
            S[j][0] *= 0.125f; S[j][1] *= 0.125f; S[j][2] *= 0.125f; S[j][3] *= 0.125f;
            nm0 = fmaxf(nm0, fmaxf(S[j][0], S[j][1]));
            nm1 = fmaxf(nm1, fmaxf(S[j][2], S[j][3]));
        }
        nm0 = fmaxf(nm0, __shfl_xor_sync(0xffffffff, nm0, 1));
        nm0 = fmaxf(nm0, __shfl_xor_sync(0xffffffff, nm0, 2));
        nm1 = fmaxf(nm1, __shfl_xor_sync(0xffffffff, nm1, 1));
        nm1 = fmaxf(nm1, __shfl_xor_sync(0xffffffff, nm1, 2));
        float c0 = __expf(m0 - nm0), c1 = __expf(m1 - nm1);
        m0 = nm0; m1 = nm1;
        float s0 = 0.f, s1 = 0.f;
#pragma unroll
        for (int j = 0; j < 8; j++) {
            S[j][0] = __expf(S[j][0] - m0); S[j][1] = __expf(S[j][1] - m0);
            S[j][2] = __expf(S[j][2] - m1); S[j][3] = __expf(S[j][3] - m1);
            s0 += S[j][0] + S[j][1];
            s1 += S[j][2] + S[j][3];
        }
        s0 += __shfl_xor_sync(0xffffffff, s0, 1);
        s0 += __shfl_xor_sync(0xffffffff, s0, 2);
        s1 += __shfl_xor_sync(0xffffffff, s1, 1);
        s1 += __shfl_xor_sync(0xffffffff, s1, 2);
        sl0 = sl0 * c0 + s0;
        sl1 = sl1 * c1 + s1;
#pragma unroll
        for (int nt = 0; nt < 8; nt++) {
            O[nt][0] *= c0; O[nt][1] *= c0; O[nt][2] *= c1; O[nt][3] *= c1;
        }

#pragma unroll
        for (int kt = 0; kt < 4; kt++) {
            uint32_t ph[4], pl[4];
            split2(S[2 * kt][0],     S[2 * kt][1],     ph[0], pl[0]);
            split2(S[2 * kt][2],     S[2 * kt][3],     ph[1], pl[1]);
            split2(S[2 * kt + 1][0], S[2 * kt + 1][1], ph[2], pl[2]);
            split2(S[2 * kt + 1][2], S[2 * kt + 1][3], ph[3], pl[3]);
#pragma unroll
            for (int p = 0; p < 4; p++) {
                uint32_t vh4[4], vl4[4];
                uint32_t vd = vH + (uint32_t)(kt * 16 + l7 + g01 * 8) * 144 + (p * 16 + g23 * 8) * 2;
                ldm_x4t(vh4, vd);
                ldm_x4t(vl4, vd + AARR);
                mma16816(O[2 * p],     ph, &vh4[0]);
                mma16816(O[2 * p],     ph, &vl4[0]);
                mma16816(O[2 * p],     pl, &vh4[0]);
                mma16816(O[2 * p + 1], ph, &vh4[2]);
                mma16816(O[2 * p + 1], ph, &vl4[2]);
                mma16816(O[2 * p + 1], pl, &vh4[2]);
            }
        }
        __syncthreads();
    }

    const float i0 = 1.f / sl0, i1 = 1.f / sl1;
    const size_t rb0 = (size_t)(b * SS + qb * 128 + wid * 16 + rq) * CD + h * DD;
    const size_t rb1 = rb0 + (size_t)8 * CD;
#pragma unroll
    for (int nt = 0; nt < 8; nt++) {
        int c = nt * 8 + cq;
        uint32_t h0, l0, h1, l1;
        split2(O[nt][0] * i0, O[nt][1] * i0, h0, l0);
        split2(O[nt][2] * i1, O[nt][3] * i1, h1, l1);
        *(uint32_t*)(g_ctx_h + rb0 + c) = h0;
        *(uint32_t*)(g_ctx_l + rb0 + c) = l0;
        *(uint32_t*)(g_ctx_h + rb1 + c) = h1;
        *(uint32_t*)(g_ctx_l + rb1 + c) = l1;
    }
}

// ---------------------------------------------------------------------------
// Launch
// ---------------------------------------------------------------------------
extern "C" void kernel_launch(void* const* d_in, const int* in_sizes, int n_in,
                              void* d_out, int out_size) {
    const float* x  = (const float*)d_in[0];
    const float* Wq = (const float*)d_in[1];
    const float* Wk = (const float*)d_in[2];
    const float* Wv = (const float*)d_in[3];
    const float* Wo = (const float*)d_in[4];
    const float* bo = (const float*)d_in[5];
    const float* Aq = (const float*)d_in[6];
    const float* Bq = (const float*)d_in[7];
    const float* Ak = (const float*)d_in[8];
    const float* Bk = (const float*)d_in[9];
    const float* Av = (const float*)d_in[10];
    const float* Bv = (const float*)d_in[11];
    const float* Ao = (const float*)d_in[12];
    const float* Bo = (const float*)d_in[13];

    static __nv_bfloat16 *p_xh, *p_xl, *p_Wh, *p_Wl, *p_Woh, *p_Wol, *p_qh, *p_ql, *p_ch, *p_cl;
    static bool init = false;
    if (!init) {
        cudaGetSymbolAddress((void**)&p_xh, g_x_h);
        cudaGetSymbolAddress((void**)&p_xl, g_x_l);
        cudaGetSymbolAddress((void**)&p_Wh, g_W_h);
        cudaGetSymbolAddress((void**)&p_Wl, g_W_l);
        cudaGetSymbolAddress((void**)&p_Woh, g_Wo_h);
        cudaGetSymbolAddress((void**)&p_Wol, g_Wo_l);
        cudaGetSymbolAddress((void**)&p_qh, g_qkv_h);
        cudaGetSymbolAddress((void**)&p_ql, g_qkv_l);
        cudaGetSymbolAddress((void**)&p_ch, g_ctx_h);
        cudaGetSymbolAddress((void**)&p_cl, g_ctx_l);
        cudaFuncSetAttribute(gemm_tc<0>, cudaFuncAttributeMaxDynamicSharedMemorySize, GEMM_SMEM);
        cudaFuncSetAttribute(gemm_tc<1>, cudaFuncAttributeMaxDynamicSharedMemorySize, GEMM_SMEM);
        cudaFuncSetAttribute(attn_tc, cudaFuncAttributeMaxDynamicSharedMemorySize, ATTN_SMEM);
        init = true;
    }

    fold_qkv_kernel<<<(NQKV * CD + 255) / 256, 256>>>(Wq, Wk, Wv, Aq, Bq, Ak, Bk, Av, Bv);
    fold_o_kernel<<<(CD * CD + 255) / 256, 256>>>(Wo, Ao, Bo);
    convert_x_kernel<<<(MM * CD + 255) / 256, 256>>>(x);

    gemm_tc<0><<<dim3(NQKV / 128, MM / 128), 256, GEMM_SMEM>>>(
        p_xh, p_xl, p_Wh, p_Wl, nullptr, p_qh, p_ql, CD, NQKV, nullptr);

    attn_tc<<<dim3(SS / 128, HH, BB), 256, ATTN_SMEM>>>();

    gemm_tc<1><<<dim3(CD / 128, MM / 128), 256, GEMM_SMEM>>>(
        p_ch, p_cl, p_Woh, p_Wol, (float*)d_out, nullptr, nullptr, CD, CD, bo);
}